// round 7
// baseline (speedup 1.0000x reference)
#include <cuda_runtime.h>
#include <cstddef>
#include <cstdint>

// CapsuleLayer dynamic routing, recompute-u_hat strategy + packed f32x2 math.
// x: [64, 2048, 8], W: [32, 2048, 16, 8], out v: [64, 32, 16] (fp32)
//
// Math restructure:
//   b starts at 0 and accumulates linearly => logits at iter k are u_hat . (v1+..+vk)
//   pass0: S1 = sum_n u_hat            (c uniform = 1/32 folded into squash)
//   pass1: c = softmax_j(u_hat . v1)        -> S2
//   pass2: c = softmax_j(u_hat . (v1+v2))   -> S3 -> v3 = output
//
// This round: balanced 296-block grid (2 CTAs/SM exactly, variable n-chunks),
// 4-deep cp.async pipeline (wait_group 2), and squash fused into the pass tail
// via an atomic-ticket last-block reduction (g_S re-zeroed for graph replays).

#define B_DIM 64
#define N_DIM 2048
#define I_DIM 8
#define J_DIM 32
#define D_DIM 16

#define GX 37              // n-chunks (2048/37 = 55..56 n per block)
#define BC 8               // b's per block
#define NBLOCKS (GX * (B_DIM / BC))   // 296 = 2 * 148
#define NC_MAX 56
#define WS_STRIDE 132      // floats per W row in smem (128 + 4 pad)
#define WBUF_FLOATS (J_DIM * WS_STRIDE)       // 4224 floats per stage
#define XT_FLOATS (BC * NC_MAX * I_DIM)       // 3584
#define SMEM_FLOATS (4 * WBUF_FLOATS + XT_FLOATS + 8 * 4 * J_DIM)
#define SMEM_BYTES (SMEM_FLOATS * 4)          // 86016 B

__device__ float g_Wt[(size_t)J_DIM * N_DIM * 128];   // transposed W, [j][n][i][d]
__device__ float g_S[3][B_DIM * J_DIM * D_DIM];       // routing-pass accumulators (stay zeroed between runs)
__device__ float g_V1[B_DIM * J_DIM * D_DIM];         // v1
__device__ float g_V12[B_DIM * J_DIM * D_DIM];        // v1 + v2
__device__ unsigned g_cnt[3];                         // pass completion tickets (stay zeroed)

typedef unsigned long long ull;

__device__ __forceinline__ ull f2_fma(ull a, ull b, ull c) {
    ull d; asm("fma.rn.f32x2 %0, %1, %2, %3;" : "=l"(d) : "l"(a), "l"(b), "l"(c)); return d;
}
__device__ __forceinline__ ull f2_mul(ull a, ull b) {
    ull d; asm("mul.rn.f32x2 %0, %1, %2;" : "=l"(d) : "l"(a), "l"(b)); return d;
}
__device__ __forceinline__ ull f2_add(ull a, ull b) {
    ull d; asm("add.rn.f32x2 %0, %1, %2;" : "=l"(d) : "l"(a), "l"(b)); return d;
}
__device__ __forceinline__ ull f2_dup(float x) {
    ull d; asm("mov.b64 %0, {%1, %1};" : "=l"(d) : "f"(x)); return d;
}
__device__ __forceinline__ void f2_unpack(ull v, float& lo, float& hi) {
    asm("mov.b64 {%0, %1}, %2;" : "=f"(lo), "=f"(hi) : "l"(v));
}
__device__ __forceinline__ float f2_hsum(ull v) {
    float lo, hi; f2_unpack(v, lo, hi); return lo + hi;
}

__device__ __forceinline__ float warp_sum32(float v) {
#pragma unroll
    for (int o = 16; o; o >>= 1) v += __shfl_xor_sync(0xffffffffu, v, o);
    return v;
}

__device__ __forceinline__ void cp16(void* dst_smem, const void* src) {
    uint32_t d = (uint32_t)__cvta_generic_to_shared(dst_smem);
    asm volatile("cp.async.cg.shared.global [%0], [%1], 16;" :: "r"(d), "l"(src));
}
__device__ __forceinline__ void cp_commit() { asm volatile("cp.async.commit_group;"); }
__device__ __forceinline__ void cp_wait2()  { asm volatile("cp.async.wait_group 2;"); }

// Transpose W[j][n][d][i] -> g_Wt[j][n][i][d]. 8 (j,n)-rows per block.
__global__ void transform_kernel(const float* __restrict__ W) {
    __shared__ float s[8][WS_STRIDE];
    const int t = threadIdx.x;
    const int r = t >> 5;          // row within block (warp per row)
    const int l = t & 31;
    const size_t row = (size_t)blockIdx.x * 8 + r;

    const float4* src = reinterpret_cast<const float4*>(W + row * 128);
    *reinterpret_cast<float4*>(&s[r][l * 4]) = __ldg(src + l);
    __syncthreads();

    const int i = l >> 2, dq = l & 3;
    float4 o;
    o.x = s[r][(dq * 4 + 0) * I_DIM + i];
    o.y = s[r][(dq * 4 + 1) * I_DIM + i];
    o.z = s[r][(dq * 4 + 2) * I_DIM + i];
    o.w = s[r][(dq * 4 + 3) * I_DIM + i];
    *reinterpret_cast<float4*>(&g_Wt[row * 128 + l * 4]) = o;
}

// Block: 256 threads. lane = j (0..31). warp w: dq = w&3 (d-quarter), rep = w>>2.
// Each thread handles 4 b's (bbase + rep*4 + bs) x 4 d's (dq*4..dq*4+3) as f32x2 pairs.
// W rows (from g_Wt) in a 4-stage cp.async pipeline; x tile staged once.
// Last-finishing block performs the squash (atomic ticket) and re-zeroes g_S.
__global__ __launch_bounds__(256, 2) void pass_kernel(
    const float* __restrict__ x, int pass, float* __restrict__ out)
{
    extern __shared__ float smem[];
    float* Wb    = smem;                          // 4 stages x 4224 floats
    float* xtile = smem + 4 * WBUF_FLOATS;        // [b][nn][i], stride 8*len floats
    float* tbp   = xtile + XT_FLOATS;             // [warp][bslot][j] = [8][4][32]

    const int t    = threadIdx.x;
    const int j    = t & 31;
    const int warp = t >> 5;
    const int dq   = warp & 3;              // d-quarter
    const int rep  = warp >> 2;             // 0..1

    const int bbase   = blockIdx.y * BC;
    const int n_start = (blockIdx.x * N_DIM) / GX;
    const int n_end   = ((blockIdx.x + 1) * N_DIM) / GX;
    const int len     = n_end - n_start;    // 55 or 56

    // W staging role: thread stages row sj, chunks sp*4 + k*32 (conflict-free)
    const int sj = t >> 3;
    const int sp = t & 7;
    const float* wsrc_base = g_Wt + (size_t)sj * N_DIM * 128 + (size_t)n_start * 128 + sp * 4;
    float* wdst_base = Wb + sj * WS_STRIDE + sp * 4;

    // ---- prologue: x tile + W stage 0 (group), then stages 1, 2 ----
    {
        const int row_f4 = 2 * len;                   // float4 per b-row
        const int tot_f4 = BC * row_f4;
        #pragma unroll
        for (int r = 0; r < 4; ++r) {
            int f = t + r * 256;
            if (f < tot_f4) {
                int b_off = f / row_f4;
                int rem   = f - b_off * row_f4;
                cp16(&xtile[(size_t)b_off * (len * I_DIM) + rem * 4],
                     x + ((size_t)(bbase + b_off) * N_DIM + n_start) * I_DIM + rem * 4);
            }
        }
        #pragma unroll
        for (int k = 0; k < 4; ++k) cp16(wdst_base + k * 32, wsrc_base + k * 32);
        cp_commit();
        #pragma unroll
        for (int k = 0; k < 4; ++k)
            cp16(wdst_base + 1 * WBUF_FLOATS + k * 32, wsrc_base + (size_t)1 * 128 + k * 32);
        cp_commit();
        #pragma unroll
        for (int k = 0; k < 4; ++k)
            cp16(wdst_base + 2 * WBUF_FLOATS + k * 32, wsrc_base + (size_t)2 * 128 + k * 32);
        cp_commit();
    }

    // v (packed pairs) for this thread's 4 b's, j, d-quarter
    ull V2[4][2];
    if (pass != 0) {
        const float* Vp = (pass == 1) ? g_V1 : g_V12;
        #pragma unroll
        for (int bs = 0; bs < 4; ++bs) {
            const ull* p = reinterpret_cast<const ull*>(
                Vp + ((size_t)(bbase + rep * 4 + bs) * J_DIM + j) * D_DIM + dq * 4);
            V2[bs][0] = p[0]; V2[bs][1] = p[1];
        }
    }

    ull acc2[4][2];
    #pragma unroll
    for (int bs = 0; bs < 4; ++bs) { acc2[bs][0] = 0ull; acc2[bs][1] = 0ull; }

    const int xstride = len * I_DIM;

    for (int nn = 0; nn < len; ++nn) {
        cp_wait2();          // stage nn (and x for nn==0) has landed
        __syncthreads();     // all warps done reading the buffer we're about to refill

        if (nn + 3 < len) {  // prefetch stage nn+3 (overlaps compute)
            float* dst = wdst_base + ((nn + 3) & 3) * WBUF_FLOATS;
            const float* src = wsrc_base + (size_t)(nn + 3) * 128;
            #pragma unroll
            for (int k = 0; k < 4; ++k) cp16(dst + k * 32, src + k * 32);
            cp_commit();
        }

        // x for 4 b's (broadcast smem reads)
        float xs[4][8];
        #pragma unroll
        for (int bs = 0; bs < 4; ++bs) {
            const float4* xp = reinterpret_cast<const float4*>(
                &xtile[(size_t)(rep * 4 + bs) * xstride + nn * I_DIM]);
            float4 a = xp[0], b = xp[1];
            xs[bs][0] = a.x; xs[bs][1] = a.y; xs[bs][2] = a.z; xs[bs][3] = a.w;
            xs[bs][4] = b.x; xs[bs][5] = b.y; xs[bs][6] = b.z; xs[bs][7] = b.w;
        }

        // u_hat (packed d-pairs): stage layout [i][d], quarter = dq*4..dq*4+3
        const float* Wc = Wb + (nn & 3) * WBUF_FLOATS + j * WS_STRIDE + dq * 4;
        ull u2[4][2];
        {
            ulonglong2 wv = *reinterpret_cast<const ulonglong2*>(Wc);
            #pragma unroll
            for (int bs = 0; bs < 4; ++bs) {
                ull xd = f2_dup(xs[bs][0]);
                u2[bs][0] = f2_mul(wv.x, xd);
                u2[bs][1] = f2_mul(wv.y, xd);
            }
        }
        #pragma unroll
        for (int i = 1; i < 8; ++i) {
            ulonglong2 wv = *reinterpret_cast<const ulonglong2*>(Wc + i * 16);
            #pragma unroll
            for (int bs = 0; bs < 4; ++bs) {
                ull xd = f2_dup(xs[bs][i]);
                u2[bs][0] = f2_fma(wv.x, xd, u2[bs][0]);
                u2[bs][1] = f2_fma(wv.y, xd, u2[bs][1]);
            }
        }

        if (pass != 0) {
            // logit partial over this d-quarter -> exchange -> softmax over j
            float* tw = tbp + warp * (4 * J_DIM);
            #pragma unroll
            for (int bs = 0; bs < 4; ++bs)
                tw[bs * J_DIM + j] = f2_hsum(f2_fma(u2[bs][0], V2[bs][0],
                                                    f2_mul(u2[bs][1], V2[bs][1])));
            asm volatile("bar.sync %0, 128;" :: "r"(1 + rep) : "memory");
            const float* tg = tbp + (rep * 4) * (4 * J_DIM);
            #pragma unroll
            for (int bs = 0; bs < 4; ++bs) {
                float tt = tg[0 * 128 + bs * J_DIM + j] + tg[1 * 128 + bs * J_DIM + j]
                         + tg[2 * 128 + bs * J_DIM + j] + tg[3 * 128 + bs * J_DIM + j];
                // logits are O(1): softmax without max-subtraction is safe here
                float e = __expf(tt);
                float z = warp_sum32(e);
                ull c2 = f2_dup(__fdividef(e, z));
                acc2[bs][0] = f2_fma(c2, u2[bs][0], acc2[bs][0]);
                acc2[bs][1] = f2_fma(c2, u2[bs][1], acc2[bs][1]);
            }
        } else {
            #pragma unroll
            for (int bs = 0; bs < 4; ++bs) {
                acc2[bs][0] = f2_add(acc2[bs][0], u2[bs][0]);
                acc2[bs][1] = f2_add(acc2[bs][1], u2[bs][1]);
            }
        }
    }

    float* S = g_S[pass];
    #pragma unroll
    for (int bs = 0; bs < 4; ++bs) {
        float* dst = &S[((size_t)(bbase + rep * 4 + bs) * J_DIM + j) * D_DIM + dq * 4];
        float a, b, c, d;
        f2_unpack(acc2[bs][0], a, b);
        f2_unpack(acc2[bs][1], c, d);
        atomicAdd(dst + 0, a);
        atomicAdd(dst + 1, b);
        atomicAdd(dst + 2, c);
        atomicAdd(dst + 3, d);
    }

    // ---- fused squash: last block to finish does it, then re-zeroes state ----
    __shared__ int s_last;
    __threadfence();
    if (t == 0) {
        unsigned tk = atomicAdd(&g_cnt[pass], 1u);
        s_last = (tk == (unsigned)(NBLOCKS - 1));
    }
    __syncthreads();
    if (s_last) {
        const float scale = (pass == 0) ? (1.0f / 32.0f) : 1.0f;
        #pragma unroll
        for (int k = 0; k < 8; ++k) {
            int idx = t + k * 256;               // (b*32 + j), 2048 total
            float4* Sp = reinterpret_cast<float4*>(&S[(size_t)idx * D_DIM]);
            float4 r0 = __ldcg(Sp + 0), r1 = __ldcg(Sp + 1);
            float4 r2 = __ldcg(Sp + 2), r3 = __ldcg(Sp + 3);
            float sv[16] = {r0.x,r0.y,r0.z,r0.w, r1.x,r1.y,r1.z,r1.w,
                            r2.x,r2.y,r2.z,r2.w, r3.x,r3.y,r3.z,r3.w};
            float ssq = 0.0f;
            #pragma unroll
            for (int d = 0; d < 16; ++d) { sv[d] *= scale; ssq = fmaf(sv[d], sv[d], ssq); }
            float inv = rsqrtf(ssq + 1e-7f);
            #pragma unroll
            for (int d = 0; d < 16; ++d) {
                float val = sv[d] * inv;
                if (pass == 0)      g_V1[(size_t)idx * D_DIM + d] = val;
                else if (pass == 1) g_V12[(size_t)idx * D_DIM + d] = g_V1[(size_t)idx * D_DIM + d] + val;
                else                out[(size_t)idx * D_DIM + d] = val;
            }
            // re-zero accumulator for the next graph replay
            float4 z4 = make_float4(0.f, 0.f, 0.f, 0.f);
            Sp[0] = z4; Sp[1] = z4; Sp[2] = z4; Sp[3] = z4;
        }
        if (t == 0) g_cnt[pass] = 0u;            // reset ticket for next replay
    }
}

extern "C" void kernel_launch(void* const* d_in, const int* in_sizes, int n_in,
                              void* d_out, int out_size) {
    const float* x = (const float*)d_in[0];
    const float* W = (const float*)d_in[1];
    // robust to input ordering: x has 64*2048*8 = 1048576 elements
    if (in_sizes[0] != B_DIM * N_DIM * I_DIM) {
        x = (const float*)d_in[1];
        W = (const float*)d_in[0];
    }
    float* out = (float*)d_out;

    cudaFuncSetAttribute(pass_kernel,
                         cudaFuncAttributeMaxDynamicSharedMemorySize, SMEM_BYTES);

    dim3 grid(GX, B_DIM / BC);   // (37, 8) = 296 blocks = exactly 2 per SM

    transform_kernel<<<(J_DIM * N_DIM) / 8, 256>>>(W);
    pass_kernel<<<grid, 256, SMEM_BYTES>>>(x, 0, out);
    pass_kernel<<<grid, 256, SMEM_BYTES>>>(x, 1, out);
    pass_kernel<<<grid, 256, SMEM_BYTES>>>(x, 2, out);
}

// round 9
// speedup vs baseline: 1.2000x; 1.2000x over previous
#include <cuda_runtime.h>
#include <cstddef>
#include <cstdint>

// CapsuleLayer dynamic routing, recompute-u_hat strategy + packed f32x2 math.
// x: [64, 2048, 8], W: [32, 2048, 16, 8], out v: [64, 32, 16] (fp32)
//
// Math restructure:
//   b starts at 0 and accumulates linearly => logits at iter k are u_hat . (v1+..+vk)
//   pass0: S1 = sum_n u_hat            (c uniform = 1/32 folded into squash)
//   pass1: c = softmax_j(u_hat . v1)        -> S2
//   pass2: c = softmax_j(u_hat . (v1+v2))   -> S3 -> v3 = output
//
// R9: R8 minus redux.sync.add.f32 (NOT supported on sm_103 — integer-only
// there); softmax sum uses 4 interleaved shfl butterflies instead (independent
// chains pipeline). Keeps: float4-packed logit exchange, 3-stage cp.async
// pipeline, 512-block work-stealing grid, separate squash.

#define B_DIM 64
#define N_DIM 2048
#define I_DIM 8
#define J_DIM 32
#define D_DIM 16

#define NC 32              // n's per block
#define BC 8               // b's per block
#define WS_STRIDE 132      // floats per W row in smem (128 + 4 pad)
#define WBUF_FLOATS (J_DIM * WS_STRIDE)       // 4224 floats per stage
#define XT_FLOATS (BC * NC * I_DIM)           // 2048
#define TB_FLOATS (8 * J_DIM * 4)             // 1024 ([warp][j] float4)
#define SMEM_FLOATS (3 * WBUF_FLOATS + XT_FLOATS + TB_FLOATS)
#define SMEM_BYTES (SMEM_FLOATS * 4)          // 62976 B -> 2 CTAs/SM

__device__ float g_Wt[(size_t)J_DIM * N_DIM * 128];   // transposed W, [j][n][i][d]
__device__ float g_S[3][B_DIM * J_DIM * D_DIM];       // routing-pass accumulators
__device__ float g_V1[B_DIM * J_DIM * D_DIM];         // v1
__device__ float g_V12[B_DIM * J_DIM * D_DIM];        // v1 + v2

typedef unsigned long long ull;

__device__ __forceinline__ ull f2_fma(ull a, ull b, ull c) {
    ull d; asm("fma.rn.f32x2 %0, %1, %2, %3;" : "=l"(d) : "l"(a), "l"(b), "l"(c)); return d;
}
__device__ __forceinline__ ull f2_mul(ull a, ull b) {
    ull d; asm("mul.rn.f32x2 %0, %1, %2;" : "=l"(d) : "l"(a), "l"(b)); return d;
}
__device__ __forceinline__ ull f2_add(ull a, ull b) {
    ull d; asm("add.rn.f32x2 %0, %1, %2;" : "=l"(d) : "l"(a), "l"(b)); return d;
}
__device__ __forceinline__ ull f2_dup(float x) {
    ull d; asm("mov.b64 %0, {%1, %1};" : "=l"(d) : "f"(x)); return d;
}
__device__ __forceinline__ void f2_unpack(ull v, float& lo, float& hi) {
    asm("mov.b64 {%0, %1}, %2;" : "=f"(lo), "=f"(hi) : "l"(v));
}
__device__ __forceinline__ float f2_hsum(ull v) {
    float lo, hi; f2_unpack(v, lo, hi); return lo + hi;
}

__device__ __forceinline__ void cp16(void* dst_smem, const void* src) {
    uint32_t d = (uint32_t)__cvta_generic_to_shared(dst_smem);
    asm volatile("cp.async.cg.shared.global [%0], [%1], 16;" :: "r"(d), "l"(src));
}
__device__ __forceinline__ void cp_commit() { asm volatile("cp.async.commit_group;"); }
__device__ __forceinline__ void cp_wait1()  { asm volatile("cp.async.wait_group 1;"); }

__global__ void init_zero_kernel() {
    int i = blockIdx.x * blockDim.x + threadIdx.x;
    if (i < 3 * B_DIM * J_DIM * D_DIM) ((float*)g_S)[i] = 0.0f;
}

// Transpose W[j][n][d][i] -> g_Wt[j][n][i][d]. 8 (j,n)-rows per block.
__global__ void transform_kernel(const float* __restrict__ W) {
    __shared__ float s[8][WS_STRIDE];
    const int t = threadIdx.x;
    const int r = t >> 5;
    const int l = t & 31;
    const size_t row = (size_t)blockIdx.x * 8 + r;

    const float4* src = reinterpret_cast<const float4*>(W + row * 128);
    *reinterpret_cast<float4*>(&s[r][l * 4]) = __ldg(src + l);
    __syncthreads();

    const int i = l >> 2, dq = l & 3;
    float4 o;
    o.x = s[r][(dq * 4 + 0) * I_DIM + i];
    o.y = s[r][(dq * 4 + 1) * I_DIM + i];
    o.z = s[r][(dq * 4 + 2) * I_DIM + i];
    o.w = s[r][(dq * 4 + 3) * I_DIM + i];
    *reinterpret_cast<float4*>(&g_Wt[row * 128 + l * 4]) = o;
}

// Block: 256 threads. lane = j (0..31). warp w: dq = w&3 (d-quarter), rep = w>>2.
// Each thread handles 4 b's (bbase + rep*4 + bs) x 4 d's (dq*4..dq*4+3) as f32x2 pairs.
// W rows (from g_Wt) in a 3-stage cp.async pipeline; x tile staged once.
__global__ __launch_bounds__(256, 2) void pass_kernel(
    const float* __restrict__ x, int pass)
{
    extern __shared__ float smem[];
    float*  Wb    = smem;                          // 3 stages x 4224 floats
    float*  xtile = smem + 3 * WBUF_FLOATS;        // [b][nn][i] : 2048 floats
    float4* tbf   = reinterpret_cast<float4*>(xtile + XT_FLOATS); // [warp*32+j]

    const int t    = threadIdx.x;
    const int j    = t & 31;
    const int warp = t >> 5;
    const int dq   = warp & 3;              // d-quarter
    const int rep  = warp >> 2;             // 0..1

    const int bbase  = blockIdx.y * BC;
    const int n_base = blockIdx.x * NC;

    // W staging: thread stages row sj, chunks sp*4 + k*32 (conflict-free)
    const int sj = t >> 3;
    const int sp = t & 7;
    const float* wsrc_base = g_Wt + (size_t)sj * N_DIM * 128 + (size_t)n_base * 128 + sp * 4;
    float* wdst_base = Wb + sj * WS_STRIDE + sp * 4;

    // ---- prologue: x tile + W stage 0 (group 0), stage 1 (group 1) ----
    #pragma unroll
    for (int r = 0; r < 2; ++r) {
        int f = t + r * 256;
        int b_off = f >> 6;
        int rem   = f & 63;
        cp16(&xtile[b_off * (NC * I_DIM) + rem * 4],
             x + ((size_t)(bbase + b_off) * N_DIM + n_base) * I_DIM + rem * 4);
    }
    #pragma unroll
    for (int k = 0; k < 4; ++k) cp16(wdst_base + k * 32, wsrc_base + k * 32);
    cp_commit();
    #pragma unroll
    for (int k = 0; k < 4; ++k)
        cp16(wdst_base + WBUF_FLOATS + k * 32, wsrc_base + (size_t)128 + k * 32);
    cp_commit();

    // v (packed pairs) for this thread's 4 b's, j, d-quarter
    ull V2[4][2];
    if (pass != 0) {
        const float* Vp = (pass == 1) ? g_V1 : g_V12;
        #pragma unroll
        for (int bs = 0; bs < 4; ++bs) {
            const ull* p = reinterpret_cast<const ull*>(
                Vp + ((size_t)(bbase + rep * 4 + bs) * J_DIM + j) * D_DIM + dq * 4);
            V2[bs][0] = p[0]; V2[bs][1] = p[1];
        }
    }

    ull acc2[4][2];
    #pragma unroll
    for (int bs = 0; bs < 4; ++bs) { acc2[bs][0] = 0ull; acc2[bs][1] = 0ull; }

    for (int nn = 0; nn < NC; ++nn) {
        cp_wait1();          // stage nn (and x for nn==0) landed
        __syncthreads();     // all warps done with the buffer being refilled

        // prefetch stage nn+2 into buffer (nn+2)%3 (overlaps compute)
        if (nn + 2 < NC) {
            float* dst = wdst_base + ((nn + 2) % 3) * WBUF_FLOATS;
            const float* src = wsrc_base + (size_t)(nn + 2) * 128;
            #pragma unroll
            for (int k = 0; k < 4; ++k) cp16(dst + k * 32, src + k * 32);
        }
        cp_commit();

        // x for 4 b's (broadcast smem reads)
        float xs[4][8];
        #pragma unroll
        for (int bs = 0; bs < 4; ++bs) {
            const float4* xp = reinterpret_cast<const float4*>(
                &xtile[(rep * 4 + bs) * (NC * I_DIM) + nn * I_DIM]);
            float4 a = xp[0], b = xp[1];
            xs[bs][0] = a.x; xs[bs][1] = a.y; xs[bs][2] = a.z; xs[bs][3] = a.w;
            xs[bs][4] = b.x; xs[bs][5] = b.y; xs[bs][6] = b.z; xs[bs][7] = b.w;
        }

        // u_hat (packed d-pairs): stage layout [i][d], quarter = dq*4..dq*4+3
        const float* Wc = Wb + (nn % 3) * WBUF_FLOATS + j * WS_STRIDE + dq * 4;
        ull u2[4][2];
        {
            ulonglong2 wv = *reinterpret_cast<const ulonglong2*>(Wc);
            #pragma unroll
            for (int bs = 0; bs < 4; ++bs) {
                ull xd = f2_dup(xs[bs][0]);
                u2[bs][0] = f2_mul(wv.x, xd);
                u2[bs][1] = f2_mul(wv.y, xd);
            }
        }
        #pragma unroll
        for (int i = 1; i < 8; ++i) {
            ulonglong2 wv = *reinterpret_cast<const ulonglong2*>(Wc + i * 16);
            #pragma unroll
            for (int bs = 0; bs < 4; ++bs) {
                ull xd = f2_dup(xs[bs][i]);
                u2[bs][0] = f2_fma(wv.x, xd, u2[bs][0]);
                u2[bs][1] = f2_fma(wv.y, xd, u2[bs][1]);
            }
        }

        if (pass != 0) {
            // logit partials over this d-quarter, packed exchange (one STS.128)
            float4 part;
            part.x = f2_hsum(f2_fma(u2[0][0], V2[0][0], f2_mul(u2[0][1], V2[0][1])));
            part.y = f2_hsum(f2_fma(u2[1][0], V2[1][0], f2_mul(u2[1][1], V2[1][1])));
            part.z = f2_hsum(f2_fma(u2[2][0], V2[2][0], f2_mul(u2[2][1], V2[2][1])));
            part.w = f2_hsum(f2_fma(u2[3][0], V2[3][0], f2_mul(u2[3][1], V2[3][1])));
            tbf[warp * 32 + j] = part;
            asm volatile("bar.sync %0, 128;" :: "r"(1 + rep) : "memory");
            const int wg = rep * 4;
            float4 a0 = tbf[(wg + 0) * 32 + j];
            float4 a1 = tbf[(wg + 1) * 32 + j];
            float4 a2 = tbf[(wg + 2) * 32 + j];
            float4 a3 = tbf[(wg + 3) * 32 + j];
            // logits are O(1): softmax without max-subtraction is safe here
            float e0 = __expf((a0.x + a1.x) + (a2.x + a3.x));
            float e1 = __expf((a0.y + a1.y) + (a2.y + a3.y));
            float e2 = __expf((a0.z + a1.z) + (a2.z + a3.z));
            float e3 = __expf((a0.w + a1.w) + (a2.w + a3.w));
            // 4 interleaved butterflies: independent chains pipeline in the SHFL unit
            float z0 = e0, z1 = e1, z2 = e2, z3 = e3;
            #pragma unroll
            for (int o = 16; o; o >>= 1) {
                z0 += __shfl_xor_sync(0xffffffffu, z0, o);
                z1 += __shfl_xor_sync(0xffffffffu, z1, o);
                z2 += __shfl_xor_sync(0xffffffffu, z2, o);
                z3 += __shfl_xor_sync(0xffffffffu, z3, o);
            }
            ull c2;
            c2 = f2_dup(__fdividef(e0, z0));
            acc2[0][0] = f2_fma(c2, u2[0][0], acc2[0][0]);
            acc2[0][1] = f2_fma(c2, u2[0][1], acc2[0][1]);
            c2 = f2_dup(__fdividef(e1, z1));
            acc2[1][0] = f2_fma(c2, u2[1][0], acc2[1][0]);
            acc2[1][1] = f2_fma(c2, u2[1][1], acc2[1][1]);
            c2 = f2_dup(__fdividef(e2, z2));
            acc2[2][0] = f2_fma(c2, u2[2][0], acc2[2][0]);
            acc2[2][1] = f2_fma(c2, u2[2][1], acc2[2][1]);
            c2 = f2_dup(__fdividef(e3, z3));
            acc2[3][0] = f2_fma(c2, u2[3][0], acc2[3][0]);
            acc2[3][1] = f2_fma(c2, u2[3][1], acc2[3][1]);
        } else {
            #pragma unroll
            for (int bs = 0; bs < 4; ++bs) {
                acc2[bs][0] = f2_add(acc2[bs][0], u2[bs][0]);
                acc2[bs][1] = f2_add(acc2[bs][1], u2[bs][1]);
            }
        }
    }

    float* S = g_S[pass];
    #pragma unroll
    for (int bs = 0; bs < 4; ++bs) {
        float* dst = &S[((size_t)(bbase + rep * 4 + bs) * J_DIM + j) * D_DIM + dq * 4];
        float a, b, c, d;
        f2_unpack(acc2[bs][0], a, b);
        f2_unpack(acc2[bs][1], c, d);
        atomicAdd(dst + 0, a);
        atomicAdd(dst + 1, b);
        atomicAdd(dst + 2, c);
        atomicAdd(dst + 3, d);
    }
}

// squash + bookkeeping between passes. idx = (b*32 + j).
__global__ void squash_kernel(int pass, float* __restrict__ out) {
    int idx = blockIdx.x * blockDim.x + threadIdx.x;
    if (idx >= B_DIM * J_DIM) return;
    const float* S = g_S[pass];
    const float scale = (pass == 0) ? (1.0f / 32.0f) : 1.0f;
    float s[D_DIM];
    float ssq = 0.0f;
#pragma unroll
    for (int d = 0; d < D_DIM; ++d) {
        float v = S[idx * D_DIM + d] * scale;
        s[d] = v;
        ssq = fmaf(v, v, ssq);
    }
    float inv = rsqrtf(ssq + 1e-7f);
#pragma unroll
    for (int d = 0; d < D_DIM; ++d) {
        float val = s[d] * inv;
        if (pass == 0)      g_V1[idx * D_DIM + d] = val;
        else if (pass == 1) g_V12[idx * D_DIM + d] = g_V1[idx * D_DIM + d] + val;
        else                out[idx * D_DIM + d] = val;
    }
}

extern "C" void kernel_launch(void* const* d_in, const int* in_sizes, int n_in,
                              void* d_out, int out_size) {
    const float* x = (const float*)d_in[0];
    const float* W = (const float*)d_in[1];
    // robust to input ordering: x has 64*2048*8 = 1048576 elements
    if (in_sizes[0] != B_DIM * N_DIM * I_DIM) {
        x = (const float*)d_in[1];
        W = (const float*)d_in[0];
    }
    float* out = (float*)d_out;

    cudaFuncSetAttribute(pass_kernel,
                         cudaFuncAttributeMaxDynamicSharedMemorySize, SMEM_BYTES);

    dim3 grid(N_DIM / NC, B_DIM / BC);   // (64, 8) = 512 blocks (work-stealing slack)

    init_zero_kernel<<<96, 1024>>>();
    transform_kernel<<<(J_DIM * N_DIM) / 8, 256>>>(W);
    pass_kernel<<<grid, 256, SMEM_BYTES>>>(x, 0);
    squash_kernel<<<8, 256>>>(0, out);
    pass_kernel<<<grid, 256, SMEM_BYTES>>>(x, 1);
    squash_kernel<<<8, 256>>>(1, out);
    pass_kernel<<<grid, 256, SMEM_BYTES>>>(x, 2);
    squash_kernel<<<2, 1024>>>(2, out);
}